// round 12
// baseline (speedup 1.0000x reference)
#include <cuda_runtime.h>
#include <cuda_fp16.h>
#include <math.h>

// ---------------- problem constants ----------------
#define NN     20000
#define EE     160000
#define FEE    500000
#define HC     64
#define HEADS  4
#define HEADC  16
#define DV     16
#define KHOP   3
#define NUMT   128
#define CSTADD 1e-5f
#define MROW   1088   // halves per node row: 1024 M + 64 Kf

// ---------------- scratch (static device globals; no allocs) ----------------
__device__ __half g_Mh[2][(size_t)NN * MROW]; // ping-pong M+Kf rows, fp16
__device__ float g_Q[NN * HC];
__device__ float g_hid[NN * HC];        // per-head hidden accumulator [N,4,16]
__device__ float g_hid16[NN * 16];      // after Wo projection
__device__ float g_temb[NUMT * HC];     // timestep-embedding MLP table
__device__ int   g_cnt2[2 * NN];        // [0,NN)=deg  [NN,2NN)=cur
__device__ int   g_off[NN + 1];
__device__ int2  g_edge[EE + 8];        // CSR by dest: (src row, norm bits), padded

// ---------------- helpers ----------------
__device__ __forceinline__ float oneelu(float x) {
    return x > 0.f ? 1.f + x : expf(x);
}
__device__ __forceinline__ float silu(float x) {
    return x / (1.f + expf(-x));
}

// ---------------- 2. in-degree (over col) ----------------
__global__ void k_deg(const int* __restrict__ ei) {
    int e = blockIdx.x * blockDim.x + threadIdx.x;
    if (e < EE) atomicAdd(&g_cnt2[ei[EE + e]], 1);
}

// ---------------- 3. fused: block0 = exclusive scan; blocks 1..128 = temb ----
__global__ void k_scan_temb(const float* __restrict__ Wt1, const float* __restrict__ bt1,
                            const float* __restrict__ Wt2, const float* __restrict__ bt2) {
    if (blockIdx.x == 0) {
        __shared__ int sums[1024];
        const int CH = 20;                       // 1024*20 = 20480 >= NN
        int t = threadIdx.x;
        int start = t * CH;
        int local[CH];
        int s = 0;
        #pragma unroll
        for (int i = 0; i < CH; i++) {
            int idx = start + i;
            int v = (idx < NN) ? g_cnt2[idx] : 0;
            local[i] = s;
            s += v;
        }
        sums[t] = s;
        __syncthreads();
        for (int d = 1; d < 1024; d <<= 1) {
            int v = (t >= d) ? sums[t - d] : 0;
            __syncthreads();
            sums[t] += v;
            __syncthreads();
        }
        int base = (t > 0) ? sums[t - 1] : 0;
        #pragma unroll
        for (int i = 0; i < CH; i++) {
            int idx = start + i;
            if (idx < NN) g_off[idx] = base + local[i];
        }
        if (t == 1023) g_off[NN] = sums[1023];
    } else {
        __shared__ float emb[HC];
        __shared__ float t1[4 * HC];
        __shared__ float red[256];
        int tb = blockIdx.x - 1;             // timestep value 0..127
        int t = threadIdx.x;
        if (t < 32) {
            float tt = (float)tb * (4000.0f / (float)NUMT);
            float f = expf(-logf(10000.0f) / 31.0f * (float)t);
            float a = tt * f;
            emb[t] = sinf(a);
            emb[32 + t] = cosf(a);
        }
        __syncthreads();
        if (t < 256) {
            float acc = bt1[t];
            #pragma unroll 8
            for (int k = 0; k < HC; k++) acc += emb[k] * Wt1[k * 256 + t];
            t1[t] = silu(acc);
        }
        __syncthreads();
        if (t < 256) {
            int o = t & 63, g = t >> 6;
            float acc = 0.f;
            #pragma unroll 8
            for (int k = g * 64; k < g * 64 + 64; k++) acc += t1[k] * Wt2[k * HC + o];
            red[t] = acc;
        }
        __syncthreads();
        if (t < HC)
            g_temb[tb * HC + t] = bt2[t] + red[t] + red[t + 64] + red[t + 128] + red[t + 192];
    }
}

// ---------------- 4. fill CSR (+ per-edge norm), packed int2 ----------------
__global__ void k_csr(const int* __restrict__ ei) {
    int e = blockIdx.x * blockDim.x + threadIdx.x;
    if (e >= EE) return;
    int r = ei[e];            // row (source)
    int c = ei[EE + e];       // col (dest)
    int pos = atomicAdd(&g_cnt2[NN + c], 1);
    int idx = g_off[c] + pos;
    int dr = g_cnt2[r];
    float nrm = (dr > 0) ? (1.f / (float)dr) : 0.f;
    g_edge[idx] = make_int2(r, __float_as_int(nrm));
}

// ---------------- 6. per-node features: h, Q, K, V, M+Kf(fp16), hidden0 -----
__global__ __launch_bounds__(256) void k_feat(
    const float* __restrict__ x, const int* __restrict__ tsteps,
    const float* __restrict__ Wi, const float* __restrict__ bi,
    const float* __restrict__ WQ, const float* __restrict__ bQ,
    const float* __restrict__ WK, const float* __restrict__ bK,
    const float* __restrict__ WV, const float* __restrict__ bV,
    const float* __restrict__ hopwise)
{
    __shared__ float sh[8][1280];        // per warp: xs[512] hs[256] ks[256] vs[256]
    int wl = threadIdx.x >> 5, l = threadIdx.x & 31;
    float* xs = sh[wl];
    float* hs = xs + 512;
    float* ks = hs + 256;
    float* vs = ks + 256;
    int nb = (blockIdx.x * 8 + wl) * 4;  // first of 4 nodes
    float hw0 = hopwise[0];
    int c0 = 2 * l;

    #pragma unroll
    for (int nn = 0; nn < 4; nn++) {
        int n = nb + nn;
        #pragma unroll
        for (int r = 0; r < 4; r++)
            xs[nn * 128 + l + 32 * r] = x[n * 128 + l + 32 * r];
    }
    __syncwarp();

    float a0[4], a1[4];
    #pragma unroll
    for (int nn = 0; nn < 4; nn++) {
        int n = nb + nn;
        int tt = tsteps[n];
        float2 te = *(const float2*)(g_temb + tt * HC + c0);
        float2 bb = *(const float2*)(bi + c0);
        a0[nn] = bb.x + te.x;
        a1[nn] = bb.y + te.y;
    }
    for (int k = 0; k < 128; k += 4) {
        float2 w0 = *(const float2*)(Wi + (k + 0) * HC + c0);
        float2 w1 = *(const float2*)(Wi + (k + 1) * HC + c0);
        float2 w2 = *(const float2*)(Wi + (k + 2) * HC + c0);
        float2 w3 = *(const float2*)(Wi + (k + 3) * HC + c0);
        #pragma unroll
        for (int nn = 0; nn < 4; nn++) {
            float4 xv = *(const float4*)(xs + nn * 128 + k);
            a0[nn] += xv.x * w0.x + xv.y * w1.x + xv.z * w2.x + xv.w * w3.x;
            a1[nn] += xv.x * w0.y + xv.y * w1.y + xv.z * w2.y + xv.w * w3.y;
        }
    }
    #pragma unroll
    for (int nn = 0; nn < 4; nn++) {
        float2 hv;
        hv.x = fmaxf(a0[nn], 0.f);
        hv.y = fmaxf(a1[nn], 0.f);
        *(float2*)(hs + nn * 64 + c0) = hv;
    }
    __syncwarp();

    // stage 2: Q/K/V GEMV with packed f32x2 FMAs (accumulator pairs)
    unsigned long long q01[4], k01[4], v01[4];
    #pragma unroll
    for (int nn = 0; nn < 4; nn++) {
        q01[nn] = *(const unsigned long long*)(bQ + c0);
        k01[nn] = *(const unsigned long long*)(bK + c0);
        v01[nn] = *(const unsigned long long*)(bV + c0);
    }
    for (int k = 0; k < 64; k += 4) {
        unsigned long long wq[4], wk[4], wv[4];
        #pragma unroll
        for (int j = 0; j < 4; j++) {
            wq[j] = *(const unsigned long long*)(WQ + (k + j) * HC + c0);
            wk[j] = *(const unsigned long long*)(WK + (k + j) * HC + c0);
            wv[j] = *(const unsigned long long*)(WV + (k + j) * HC + c0);
        }
        #pragma unroll
        for (int nn = 0; nn < 4; nn++) {
            float4 hv = *(const float4*)(hs + nn * 64 + k);
            unsigned long long hx, hy, hz, hw_;
            asm("mov.b64 %0, {%1, %1};" : "=l"(hx)  : "f"(hv.x));
            asm("mov.b64 %0, {%1, %1};" : "=l"(hy)  : "f"(hv.y));
            asm("mov.b64 %0, {%1, %1};" : "=l"(hz)  : "f"(hv.z));
            asm("mov.b64 %0, {%1, %1};" : "=l"(hw_) : "f"(hv.w));
            asm("fma.rn.f32x2 %0, %1, %2, %0;" : "+l"(q01[nn]) : "l"(hx),  "l"(wq[0]));
            asm("fma.rn.f32x2 %0, %1, %2, %0;" : "+l"(q01[nn]) : "l"(hy),  "l"(wq[1]));
            asm("fma.rn.f32x2 %0, %1, %2, %0;" : "+l"(q01[nn]) : "l"(hz),  "l"(wq[2]));
            asm("fma.rn.f32x2 %0, %1, %2, %0;" : "+l"(q01[nn]) : "l"(hw_), "l"(wq[3]));
            asm("fma.rn.f32x2 %0, %1, %2, %0;" : "+l"(k01[nn]) : "l"(hx),  "l"(wk[0]));
            asm("fma.rn.f32x2 %0, %1, %2, %0;" : "+l"(k01[nn]) : "l"(hy),  "l"(wk[1]));
            asm("fma.rn.f32x2 %0, %1, %2, %0;" : "+l"(k01[nn]) : "l"(hz),  "l"(wk[2]));
            asm("fma.rn.f32x2 %0, %1, %2, %0;" : "+l"(k01[nn]) : "l"(hw_), "l"(wk[3]));
            asm("fma.rn.f32x2 %0, %1, %2, %0;" : "+l"(v01[nn]) : "l"(hx),  "l"(wv[0]));
            asm("fma.rn.f32x2 %0, %1, %2, %0;" : "+l"(v01[nn]) : "l"(hy),  "l"(wv[1]));
            asm("fma.rn.f32x2 %0, %1, %2, %0;" : "+l"(v01[nn]) : "l"(hz),  "l"(wv[2]));
            asm("fma.rn.f32x2 %0, %1, %2, %0;" : "+l"(v01[nn]) : "l"(hw_), "l"(wv[3]));
        }
    }
    #pragma unroll
    for (int nn = 0; nn < 4; nn++) {
        int n = nb + nn;
        float q0, q1, kk0, kk1, v0, v1;
        asm("mov.b64 {%0, %1}, %2;" : "=f"(q0),  "=f"(q1)  : "l"(q01[nn]));
        asm("mov.b64 {%0, %1}, %2;" : "=f"(kk0), "=f"(kk1) : "l"(k01[nn]));
        asm("mov.b64 {%0, %1}, %2;" : "=f"(v0),  "=f"(v1)  : "l"(v01[nn]));
        float2 t2;
        t2.x = oneelu(q0); t2.y = oneelu(q1);
        *(float2*)(g_Q + n * HC + c0) = t2;
        t2.x = oneelu(kk0); t2.y = oneelu(kk1);
        *(float2*)(ks + nn * 64 + c0) = t2;
        t2.x = v0; t2.y = v1;
        *(float2*)(vs + nn * 64 + c0) = t2;
        t2.x = v0 * hw0; t2.y = v1 * hw0;
        *(float2*)(g_hid + n * HC + c0) = t2;
    }
    __syncwarp();

    // M(fp16): slot s = p*32+l holds flats f=8s..8s+7 -> head p, i=l>>1, j0=(l&1)*8
    // Kf(fp16): half2 at row+1024+2l = channels (2l, 2l+1)
    int i_ = l >> 1, j0 = (l & 1) * 8;
    #pragma unroll
    for (int nn = 0; nn < 4; nn++) {
        int n = nb + nn;
        __half* row = g_Mh[0] + (size_t)n * MROW;
        float4* Mp = (float4*)row;
        #pragma unroll
        for (int p = 0; p < 4; p++) {
            float kv = ks[nn * 64 + p * 16 + i_];
            const float* vv = vs + nn * 64 + p * 16 + j0;
            float4 o;
            __half2* oh = reinterpret_cast<__half2*>(&o);
            oh[0] = __floats2half2_rn(kv * vv[0], kv * vv[1]);
            oh[1] = __floats2half2_rn(kv * vv[2], kv * vv[3]);
            oh[2] = __floats2half2_rn(kv * vv[4], kv * vv[5]);
            oh[3] = __floats2half2_rn(kv * vv[6], kv * vv[7]);
            Mp[p * 32 + l] = o;
        }
        ((__half2*)(row + 1024))[l] =
            __floats2half2_rn(ks[nn * 64 + c0], ks[nn * 64 + c0 + 1]);
    }
}

// ---------------- 7. hop: warp per (node, head-pair), 4-edge unroll ---------
struct Ed2 { float4 a, b; float2 kf; };

__device__ __forceinline__ Ed2 ld2(const __half* __restrict__ Min, int r, int hp, int l) {
    Ed2 d;
    const __half* row = Min + (size_t)r * MROW;
    const float4* P = (const float4*)row + hp * 64 + l;
    d.a = P[0];
    d.b = P[32];
    d.kf = __half22float2(((const __half2*)(row + 1024))[hp * 16 + (l & 15)]);
    return d;
}

__device__ __forceinline__ void acc_f16(float* acc, float4 a, float wt) {
    const __half2* h = reinterpret_cast<const __half2*>(&a);
    #pragma unroll
    for (int q = 0; q < 4; q++) {
        float2 f = __half22float2(h[q]);
        acc[2 * q]     += wt * f.x;
        acc[2 * q + 1] += wt * f.y;
    }
}

__device__ __forceinline__ void acc_e2(float acc[2][8], float& kf0, float& kf1,
                                       const Ed2& d, float wt) {
    acc_f16(acc[0], d.a, wt);
    acc_f16(acc[1], d.b, wt);
    kf0 += wt * d.kf.x;
    kf1 += wt * d.kf.y;
}

__global__ __launch_bounds__(256) void k_hop(
    const __half* __restrict__ Min, __half* __restrict__ Mout,
    const float* __restrict__ hopwise, const float* __restrict__ headwise,
    int hop, int write_m)
{
    const unsigned F = 0xffffffffu;
    __shared__ float hsm[8][32];
    int w = threadIdx.x >> 5;            // 0..7
    int l = threadIdx.x & 31;
    int n = blockIdx.x * 4 + (w >> 1);   // node
    int hp = w & 1;                      // head-pair: heads 2hp, 2hp+1

    int s = g_off[n], e = g_off[n + 1];

    float acc[2][8];
    #pragma unroll
    for (int p = 0; p < 2; p++)
        #pragma unroll
        for (int c = 0; c < 8; c++) acc[p][c] = 0.f;
    float kf0 = 0.f, kf1 = 0.f;

    const int2* __restrict__ E = g_edge;
    int k = s;
    int2 e0, e1, e2, e3;
    if (k + 3 < e) { e0 = E[k]; e1 = E[k + 1]; e2 = E[k + 2]; e3 = E[k + 3]; }
    while (k + 3 < e) {
        // prefetch next quad (array padded by 8; garbage never dereferenced)
        int2 f0 = E[k + 4], f1 = E[k + 5], f2 = E[k + 6], f3 = E[k + 7];
        Ed2 d0 = ld2(Min, e0.x, hp, l);
        Ed2 d1 = ld2(Min, e1.x, hp, l);
        Ed2 d2 = ld2(Min, e2.x, hp, l);
        Ed2 d3 = ld2(Min, e3.x, hp, l);
        acc_e2(acc, kf0, kf1, d0, __int_as_float(e0.y));
        acc_e2(acc, kf0, kf1, d1, __int_as_float(e1.y));
        acc_e2(acc, kf0, kf1, d2, __int_as_float(e2.y));
        acc_e2(acc, kf0, kf1, d3, __int_as_float(e3.y));
        k += 4;
        e0 = f0; e1 = f1; e2 = f2; e3 = f3;
    }
    for (; k < e; k++) {
        int2 p = E[k];
        Ed2 d = ld2(Min, p.x, hp, l);
        acc_e2(acc, kf0, kf1, d, __int_as_float(p.y));
    }

    // stores (skipped on last hop: Mout never read again)
    if (write_m) {
        __half* row = Mout + (size_t)n * MROW;
        float4* Qp = (float4*)row + hp * 64 + l;
        #pragma unroll
        for (int p = 0; p < 2; p++) {
            float4 o;
            __half2* oh = reinterpret_cast<__half2*>(&o);
            oh[0] = __floats2half2_rn(acc[p][0], acc[p][1]);
            oh[1] = __floats2half2_rn(acc[p][2], acc[p][3]);
            oh[2] = __floats2half2_rn(acc[p][4], acc[p][5]);
            oh[3] = __floats2half2_rn(acc[p][6], acc[p][7]);
            Qp[p * 32] = o;
        }
        if (l < 16)
            ((__half2*)(row + 1024))[hp * 16 + l] = __floats2half2_rn(kf0, kf1);
    }

    // ---- epilogue: H = Q·M, C = Q·Kf, hidden += gamma/C * H -----------------
    // lane (l&15) holds Kf channels (32hp+2(l&15), +1); Q loaded to match.
    float2 q2 = *(const float2*)(g_Q + n * HC + 32 * hp + 2 * (l & 15));
    float qa = q2.x, qb = q2.y;

    // C per local head u: channels 16u..16u+15 <-> lanes 8u..8u+7
    float t0 = qa * kf0 + qb * kf1;
    #pragma unroll
    for (int mask = 1; mask <= 4; mask <<= 1)
        t0 += __shfl_xor_sync(F, t0, mask);
    float cc[2];
    cc[0] = __shfl_sync(F, t0, 0) + CSTADD;
    cc[1] = __shfl_sync(F, t0, 8) + CSTADD;

    // gamma = hopwise[hop+1] * softmax(headwise[:,hop]); pick heads 2hp, 2hp+1
    float h0 = headwise[0 * KHOP + hop];
    float h1 = headwise[1 * KHOP + hop];
    float h2 = headwise[2 * KHOP + hop];
    float h3 = headwise[3 * KHOP + hop];
    float mx = fmaxf(fmaxf(h0, h1), fmaxf(h2, h3));
    float e0s = expf(h0 - mx), e1s = expf(h1 - mx), e2s = expf(h2 - mx), e3s = expf(h3 - mx);
    float denom = e0s + e1s + e2s + e3s;
    float hw = hopwise[hop + 1] / denom;
    float eh0 = hp ? e2s : e0s;
    float eh1 = hp ? e3s : e1s;
    float sc[2];
    sc[0] = hw * eh0 / cc[0];
    sc[1] = hw * eh1 / cc[1];

    // H: lane holds M row i=l>>1, col-block l&1 for both local heads.
    // Q[u][i_] lives at lane 8u + (i_>>1), component i_&1.
    int i_ = l >> 1;
    int so = i_ >> 1;
    int comp = i_ & 1;
    #pragma unroll
    for (int u = 0; u < 2; u++) {
        int srcl = 8 * u + so;
        float sa = __shfl_sync(F, qa, srcl);
        float sb = __shfl_sync(F, qb, srcl);
        float qi = comp ? sb : sa;
        float p0 = qi * acc[u][0], p1 = qi * acc[u][1];
        float p2 = qi * acc[u][2], p3 = qi * acc[u][3];
        float p4 = qi * acc[u][4], p5 = qi * acc[u][5];
        float p6 = qi * acc[u][6], p7 = qi * acc[u][7];
        #pragma unroll
        for (int mask = 2; mask <= 16; mask <<= 1) {
            p0 += __shfl_xor_sync(F, p0, mask);
            p1 += __shfl_xor_sync(F, p1, mask);
            p2 += __shfl_xor_sync(F, p2, mask);
            p3 += __shfl_xor_sync(F, p3, mask);
            p4 += __shfl_xor_sync(F, p4, mask);
            p5 += __shfl_xor_sync(F, p5, mask);
            p6 += __shfl_xor_sync(F, p6, mask);
            p7 += __shfl_xor_sync(F, p7, mask);
        }
        if (l < 2) {
            float g = sc[u];
            float* d = &hsm[w][u * 16 + l * 8];
            d[0] = p0 * g; d[1] = p1 * g; d[2] = p2 * g; d[3] = p3 * g;
            d[4] = p4 * g; d[5] = p5 * g; d[6] = p6 * g; d[7] = p7 * g;
        }
    }
    __syncwarp();
    if (l < 8) {
        // warp covers channels 32hp..32hp+31 = float4 slots 8hp..8hp+7
        float4* hp4 = (float4*)(g_hid + n * HC) + 8 * hp + l;
        float4 add = *((float4*)hsm[w] + l);
        float4 hv = *hp4;
        hv.x += add.x; hv.y += add.y; hv.z += add.z; hv.w += add.w;
        *hp4 = hv;
    }
}

// ---------------- 8. output projection hidden[N,64] @ Wo[64,16] + bo ----------
__global__ void k_wo(const float* __restrict__ Wo, const float* __restrict__ bo,
                     float* __restrict__ out_hidden, int write_out) {
    int idx = blockIdx.x * blockDim.x + threadIdx.x;
    if (idx >= NN * 16) return;
    int n = idx >> 4, cc = idx & 15;
    float acc = bo[cc];
    #pragma unroll 8
    for (int k = 0; k < HC; k++) acc += g_hid[n * HC + k] * Wo[k * 16 + cc];
    g_hid16[idx] = acc;
    if (write_out) out_hidden[idx] = acc;
}

// ---------------- 9. edge regression head (packed f32x2 FMA) ----------------
__global__ __launch_bounds__(256) void k_edge(
    const int* __restrict__ fei,
    const float* __restrict__ Wf1, const float* __restrict__ bf1,
    const float* __restrict__ Wf2, const float* __restrict__ bf2,
    float* __restrict__ out)
{
    __shared__ float w1[32 * 16];
    __shared__ float b1[16];
    __shared__ float w2[16];
    int t = threadIdx.x;
    for (int i = t; i < 512; i += 256) w1[i] = Wf1[i];
    if (t < 16) { b1[t] = bf1[t]; w2[t] = Wf2[t]; }
    __syncthreads();

    int e = blockIdx.x * blockDim.x + t;
    if (e >= FEE) return;
    int srow = fei[e];
    int drow = fei[FEE + e];

    float he[32];
    {
        const float4* hp = (const float4*)(g_hid16 + srow * 16);
        float4 v;
        v = hp[0]; he[0] = v.x; he[1] = v.y; he[2] = v.z; he[3] = v.w;
        v = hp[1]; he[4] = v.x; he[5] = v.y; he[6] = v.z; he[7] = v.w;
        v = hp[2]; he[8] = v.x; he[9] = v.y; he[10] = v.z; he[11] = v.w;
        v = hp[3]; he[12] = v.x; he[13] = v.y; he[14] = v.z; he[15] = v.w;
        const float4* hq = (const float4*)(g_hid16 + drow * 16);
        v = hq[0]; he[16] = v.x; he[17] = v.y; he[18] = v.z; he[19] = v.w;
        v = hq[1]; he[20] = v.x; he[21] = v.y; he[22] = v.z; he[23] = v.w;
        v = hq[2]; he[24] = v.x; he[25] = v.y; he[26] = v.z; he[27] = v.w;
        v = hq[3]; he[28] = v.x; he[29] = v.y; he[30] = v.z; he[31] = v.w;
    }

    // 16 accumulators as 8 packed f32x2
    unsigned long long acc8[8];
    {
        const unsigned long long* bu = (const unsigned long long*)b1;
        #pragma unroll
        for (int j = 0; j < 8; j++) acc8[j] = bu[j];
    }
    #pragma unroll
    for (int k = 0; k < 32; k++) {
        float hv = he[k];
        unsigned long long hv2;
        asm("mov.b64 %0, {%1, %1};" : "=l"(hv2) : "f"(hv));
        const ulonglong2* wr = (const ulonglong2*)(w1 + k * 16);
        #pragma unroll
        for (int j = 0; j < 4; j++) {
            ulonglong2 wp = wr[j];
            asm("fma.rn.f32x2 %0, %1, %2, %0;" : "+l"(acc8[2 * j])     : "l"(hv2), "l"(wp.x));
            asm("fma.rn.f32x2 %0, %1, %2, %0;" : "+l"(acc8[2 * j + 1]) : "l"(hv2), "l"(wp.y));
        }
    }
    float outv = bf2[0];
    #pragma unroll
    for (int j = 0; j < 8; j++) {
        float lo, hi;
        asm("mov.b64 {%0, %1}, %2;" : "=f"(lo), "=f"(hi) : "l"(acc8[j]));
        outv += silu(lo) * w2[2 * j] + silu(hi) * w2[2 * j + 1];
    }
    out[e] = outv;
}

// ---------------- launch ----------------
extern "C" void kernel_launch(void* const* d_in, const int* in_sizes, int n_in,
                              void* d_out, int out_size) {
    const float* x   = (const float*)d_in[0];
    const int* ei    = (const int*)d_in[1];
    const int* fei   = (const int*)d_in[2];
    const int* ts    = (const int*)d_in[3];
    const float* Wi  = (const float*)d_in[4];
    const float* bi  = (const float*)d_in[5];
    const float* Wt1 = (const float*)d_in[6];
    const float* bt1 = (const float*)d_in[7];
    const float* Wt2 = (const float*)d_in[8];
    const float* bt2 = (const float*)d_in[9];
    const float* WQ  = (const float*)d_in[10];
    const float* bQ  = (const float*)d_in[11];
    const float* WK  = (const float*)d_in[12];
    const float* bK  = (const float*)d_in[13];
    const float* WV  = (const float*)d_in[14];
    const float* bV  = (const float*)d_in[15];
    const float* Wo  = (const float*)d_in[16];
    const float* bo  = (const float*)d_in[17];
    const float* hopwise  = (const float*)d_in[18];
    const float* headwise = (const float*)d_in[19];
    const float* Wf1 = (const float*)d_in[20];
    const float* bf1 = (const float*)d_in[21];
    const float* Wf2 = (const float*)d_in[22];
    const float* bf2 = (const float*)d_in[23];
    float* out = (float*)d_out;

    static __half* pM0 = nullptr;
    static __half* pM1;
    static int* pCnt;
    if (!pM0) {
        cudaGetSymbolAddress((void**)&pM0, g_Mh);
        pM1 = pM0 + (size_t)NN * MROW;
        cudaGetSymbolAddress((void**)&pCnt, g_cnt2);
    }

    int write_hidden = (out_size >= FEE + NN * 16) ? 1 : 0;
    float* out_hidden = out + FEE;

    cudaMemsetAsync(pCnt, 0, 2 * NN * sizeof(int));

    k_deg<<<(EE + 255) / 256, 256>>>(ei);
    k_scan_temb<<<1 + NUMT, 1024>>>(Wt1, bt1, Wt2, bt2);
    k_csr<<<(EE + 255) / 256, 256>>>(ei);
    k_feat<<<NN / 32, 256>>>(x, ts, Wi, bi, WQ, bQ, WK, bK, WV, bV, hopwise);

    // hops with ping-pong buffers (warp per node-head-pair)
    k_hop<<<NN / 4, 256>>>(pM0, pM1, hopwise, headwise, 0, 1);
    k_hop<<<NN / 4, 256>>>(pM1, pM0, hopwise, headwise, 1, 1);
    k_hop<<<NN / 4, 256>>>(pM0, pM1, hopwise, headwise, 2, 0);

    k_wo<<<(NN * 16 + 255) / 256, 256>>>(Wo, bo, out_hidden, write_hidden);
    k_edge<<<(FEE + 255) / 256, 256>>>(fei, Wf1, bf1, Wf2, bf2, out);
}

// round 15
// speedup vs baseline: 1.4786x; 1.4786x over previous
#include <cuda_runtime.h>
#include <cuda_fp16.h>
#include <math.h>

// ---------------- problem constants ----------------
#define NN     20000
#define EE     160000
#define FEE    500000
#define HC     64
#define HEADS  4
#define HEADC  16
#define DV     16
#define KHOP   3
#define NUMT   128
#define CSTADD 1e-5f
#define MROW   1088   // halves per node row: 1024 M + 64 Kf

// ---------------- scratch (static device globals; no allocs) ----------------
__device__ __half g_Mh[2][(size_t)NN * MROW]; // ping-pong M+Kf rows, fp16
__device__ float g_Q[NN * HC];
__device__ float g_hid[NN * HC];        // per-head hidden accumulator [N,4,16]
__device__ float g_hid16[NN * 16];      // after Wo projection
__device__ float g_temb[NUMT * HC];     // timestep-embedding MLP table
__device__ int   g_cnt2[2 * NN];        // [0,NN)=deg  [NN,2NN)=cur
__device__ int   g_off[NN + 1];
__device__ int2  g_edge[EE + 8];        // CSR by dest: (src row, norm bits), padded

// ---------------- helpers ----------------
__device__ __forceinline__ float oneelu(float x) {
    return x > 0.f ? 1.f + x : expf(x);
}
__device__ __forceinline__ float silu(float x) {
    return x / (1.f + expf(-x));
}

// ---------------- 2. in-degree (over col) ----------------
__global__ void k_deg(const int* __restrict__ ei) {
    int e = blockIdx.x * blockDim.x + threadIdx.x;
    if (e < EE) atomicAdd(&g_cnt2[ei[EE + e]], 1);
}

// ---------------- 3. fused: block0 = exclusive scan; blocks 1..128 = temb ----
__global__ void k_scan_temb(const float* __restrict__ Wt1, const float* __restrict__ bt1,
                            const float* __restrict__ Wt2, const float* __restrict__ bt2) {
    if (blockIdx.x == 0) {
        __shared__ int sums[1024];
        const int CH = 20;                       // 1024*20 = 20480 >= NN
        int t = threadIdx.x;
        int start = t * CH;
        int local[CH];
        int s = 0;
        #pragma unroll
        for (int i = 0; i < CH; i++) {
            int idx = start + i;
            int v = (idx < NN) ? g_cnt2[idx] : 0;
            local[i] = s;
            s += v;
        }
        sums[t] = s;
        __syncthreads();
        for (int d = 1; d < 1024; d <<= 1) {
            int v = (t >= d) ? sums[t - d] : 0;
            __syncthreads();
            sums[t] += v;
            __syncthreads();
        }
        int base = (t > 0) ? sums[t - 1] : 0;
        #pragma unroll
        for (int i = 0; i < CH; i++) {
            int idx = start + i;
            if (idx < NN) g_off[idx] = base + local[i];
        }
        if (t == 1023) g_off[NN] = sums[1023];
    } else {
        __shared__ float emb[HC];
        __shared__ float t1[4 * HC];
        __shared__ float red[256];
        int tb = blockIdx.x - 1;             // timestep value 0..127
        int t = threadIdx.x;
        if (t < 32) {
            float tt = (float)tb * (4000.0f / (float)NUMT);
            float f = expf(-logf(10000.0f) / 31.0f * (float)t);
            float a = tt * f;
            emb[t] = sinf(a);
            emb[32 + t] = cosf(a);
        }
        __syncthreads();
        if (t < 256) {
            float acc = bt1[t];
            #pragma unroll 8
            for (int k = 0; k < HC; k++) acc += emb[k] * Wt1[k * 256 + t];
            t1[t] = silu(acc);
        }
        __syncthreads();
        if (t < 256) {
            int o = t & 63, g = t >> 6;
            float acc = 0.f;
            #pragma unroll 8
            for (int k = g * 64; k < g * 64 + 64; k++) acc += t1[k] * Wt2[k * HC + o];
            red[t] = acc;
        }
        __syncthreads();
        if (t < HC)
            g_temb[tb * HC + t] = bt2[t] + red[t] + red[t + 64] + red[t + 128] + red[t + 192];
    }
}

// ---------------- 4. fill CSR (+ per-edge norm), packed int2 ----------------
__global__ void k_csr(const int* __restrict__ ei) {
    int e = blockIdx.x * blockDim.x + threadIdx.x;
    if (e >= EE) return;
    int r = ei[e];            // row (source)
    int c = ei[EE + e];       // col (dest)
    int pos = atomicAdd(&g_cnt2[NN + c], 1);
    int idx = g_off[c] + pos;
    int dr = g_cnt2[r];
    float nrm = (dr > 0) ? (1.f / (float)dr) : 0.f;
    g_edge[idx] = make_int2(r, __float_as_int(nrm));
}

// ---------------- 6. per-node features: h, Q, K, V, M+Kf(fp16), hidden0 -----
__global__ __launch_bounds__(256) void k_feat(
    const float* __restrict__ x, const int* __restrict__ tsteps,
    const float* __restrict__ Wi, const float* __restrict__ bi,
    const float* __restrict__ WQ, const float* __restrict__ bQ,
    const float* __restrict__ WK, const float* __restrict__ bK,
    const float* __restrict__ WV, const float* __restrict__ bV,
    const float* __restrict__ hopwise)
{
    __shared__ float sh[8][1280];        // per warp: xs[512] hs[256] ks[256] vs[256]
    int wl = threadIdx.x >> 5, l = threadIdx.x & 31;
    float* xs = sh[wl];
    float* hs = xs + 512;
    float* ks = hs + 256;
    float* vs = ks + 256;
    int nb = (blockIdx.x * 8 + wl) * 4;  // first of 4 nodes
    float hw0 = hopwise[0];
    int c0 = 2 * l;

    #pragma unroll
    for (int nn = 0; nn < 4; nn++) {
        int n = nb + nn;
        #pragma unroll
        for (int r = 0; r < 4; r++)
            xs[nn * 128 + l + 32 * r] = x[n * 128 + l + 32 * r];
    }
    __syncwarp();

    float a0[4], a1[4];
    #pragma unroll
    for (int nn = 0; nn < 4; nn++) {
        int n = nb + nn;
        int tt = tsteps[n];
        float2 te = *(const float2*)(g_temb + tt * HC + c0);
        float2 bb = *(const float2*)(bi + c0);
        a0[nn] = bb.x + te.x;
        a1[nn] = bb.y + te.y;
    }
    for (int k = 0; k < 128; k += 4) {
        float2 w0 = *(const float2*)(Wi + (k + 0) * HC + c0);
        float2 w1 = *(const float2*)(Wi + (k + 1) * HC + c0);
        float2 w2 = *(const float2*)(Wi + (k + 2) * HC + c0);
        float2 w3 = *(const float2*)(Wi + (k + 3) * HC + c0);
        #pragma unroll
        for (int nn = 0; nn < 4; nn++) {
            float4 xv = *(const float4*)(xs + nn * 128 + k);
            a0[nn] += xv.x * w0.x + xv.y * w1.x + xv.z * w2.x + xv.w * w3.x;
            a1[nn] += xv.x * w0.y + xv.y * w1.y + xv.z * w2.y + xv.w * w3.y;
        }
    }
    #pragma unroll
    for (int nn = 0; nn < 4; nn++) {
        float2 hv;
        hv.x = fmaxf(a0[nn], 0.f);
        hv.y = fmaxf(a1[nn], 0.f);
        *(float2*)(hs + nn * 64 + c0) = hv;
    }
    __syncwarp();

    float q0[4], q1[4], kk0[4], kk1[4], v0[4], v1[4];
    #pragma unroll
    for (int nn = 0; nn < 4; nn++) {
        float2 b;
        b = *(const float2*)(bQ + c0); q0[nn] = b.x; q1[nn] = b.y;
        b = *(const float2*)(bK + c0); kk0[nn] = b.x; kk1[nn] = b.y;
        b = *(const float2*)(bV + c0); v0[nn] = b.x; v1[nn] = b.y;
    }
    for (int k = 0; k < 64; k += 4) {
        float2 wq0 = *(const float2*)(WQ + (k + 0) * HC + c0);
        float2 wq1 = *(const float2*)(WQ + (k + 1) * HC + c0);
        float2 wq2 = *(const float2*)(WQ + (k + 2) * HC + c0);
        float2 wq3 = *(const float2*)(WQ + (k + 3) * HC + c0);
        float2 wk0 = *(const float2*)(WK + (k + 0) * HC + c0);
        float2 wk1 = *(const float2*)(WK + (k + 1) * HC + c0);
        float2 wk2 = *(const float2*)(WK + (k + 2) * HC + c0);
        float2 wk3 = *(const float2*)(WK + (k + 3) * HC + c0);
        float2 wv0 = *(const float2*)(WV + (k + 0) * HC + c0);
        float2 wv1 = *(const float2*)(WV + (k + 1) * HC + c0);
        float2 wv2 = *(const float2*)(WV + (k + 2) * HC + c0);
        float2 wv3 = *(const float2*)(WV + (k + 3) * HC + c0);
        #pragma unroll
        for (int nn = 0; nn < 4; nn++) {
            float4 hv = *(const float4*)(hs + nn * 64 + k);
            q0[nn]  += hv.x * wq0.x + hv.y * wq1.x + hv.z * wq2.x + hv.w * wq3.x;
            q1[nn]  += hv.x * wq0.y + hv.y * wq1.y + hv.z * wq2.y + hv.w * wq3.y;
            kk0[nn] += hv.x * wk0.x + hv.y * wk1.x + hv.z * wk2.x + hv.w * wk3.x;
            kk1[nn] += hv.x * wk0.y + hv.y * wk1.y + hv.z * wk2.y + hv.w * wk3.y;
            v0[nn]  += hv.x * wv0.x + hv.y * wv1.x + hv.z * wv2.x + hv.w * wv3.x;
            v1[nn]  += hv.x * wv0.y + hv.y * wv1.y + hv.z * wv2.y + hv.w * wv3.y;
        }
    }
    #pragma unroll
    for (int nn = 0; nn < 4; nn++) {
        int n = nb + nn;
        float2 t2;
        t2.x = oneelu(q0[nn]); t2.y = oneelu(q1[nn]);
        *(float2*)(g_Q + n * HC + c0) = t2;
        t2.x = oneelu(kk0[nn]); t2.y = oneelu(kk1[nn]);
        *(float2*)(ks + nn * 64 + c0) = t2;
        t2.x = v0[nn]; t2.y = v1[nn];
        *(float2*)(vs + nn * 64 + c0) = t2;
        t2.x = v0[nn] * hw0; t2.y = v1[nn] * hw0;
        *(float2*)(g_hid + n * HC + c0) = t2;
    }
    __syncwarp();

    // M(fp16): slot s = p*32+l holds flats f=8s..8s+7 -> head p, i=l>>1, j0=(l&1)*8
    // Kf(fp16): half2 at row+1024+2l = channels (2l, 2l+1)
    int i_ = l >> 1, j0 = (l & 1) * 8;
    #pragma unroll
    for (int nn = 0; nn < 4; nn++) {
        int n = nb + nn;
        __half* row = g_Mh[0] + (size_t)n * MROW;
        float4* Mp = (float4*)row;
        #pragma unroll
        for (int p = 0; p < 4; p++) {
            float kv = ks[nn * 64 + p * 16 + i_];
            const float* vv = vs + nn * 64 + p * 16 + j0;
            float4 o;
            __half2* oh = reinterpret_cast<__half2*>(&o);
            oh[0] = __floats2half2_rn(kv * vv[0], kv * vv[1]);
            oh[1] = __floats2half2_rn(kv * vv[2], kv * vv[3]);
            oh[2] = __floats2half2_rn(kv * vv[4], kv * vv[5]);
            oh[3] = __floats2half2_rn(kv * vv[6], kv * vv[7]);
            Mp[p * 32 + l] = o;
        }
        ((__half2*)(row + 1024))[l] =
            __floats2half2_rn(ks[nn * 64 + c0], ks[nn * 64 + c0 + 1]);
    }
}

// ---------------- 7. one propagation hop: 2-edge unroll + index prefetch ----
struct EdgeData { float4 m0, m1, m2, m3; float2 kf; };

__device__ __forceinline__ EdgeData ld_edge(const __half* __restrict__ Min, int r, int l) {
    EdgeData d;
    const __half* row = Min + (size_t)r * MROW;
    const float4* P = (const float4*)row + l;
    d.m0 = P[0]; d.m1 = P[32]; d.m2 = P[64]; d.m3 = P[96];
    d.kf = __half22float2(((const __half2*)(row + 1024))[l]);
    return d;
}

__device__ __forceinline__ void acc_f16(float* acc, float4 a, float wt) {
    const __half2* h = reinterpret_cast<const __half2*>(&a);
    #pragma unroll
    for (int q = 0; q < 4; q++) {
        float2 f = __half22float2(h[q]);
        acc[2 * q]     += wt * f.x;
        acc[2 * q + 1] += wt * f.y;
    }
}

__device__ __forceinline__ void acc_edge(float acc[4][8], float& kfa, float& kfb,
                                         const EdgeData& d, float wt) {
    acc_f16(acc[0], d.m0, wt);
    acc_f16(acc[1], d.m1, wt);
    acc_f16(acc[2], d.m2, wt);
    acc_f16(acc[3], d.m3, wt);
    kfa += wt * d.kf.x;
    kfb += wt * d.kf.y;
}

__global__ __launch_bounds__(256) void k_hop(
    const __half* __restrict__ Min, __half* __restrict__ Mout,
    const float* __restrict__ hopwise, const float* __restrict__ headwise,
    int hop, int write_m)
{
    const unsigned F = 0xffffffffu;
    __shared__ float hsm[8][64];
    int w = threadIdx.x >> 5;
    int n = blockIdx.x * 8 + w;
    int l = threadIdx.x & 31;

    int s = g_off[n], e = g_off[n + 1];

    float acc[4][8];
    #pragma unroll
    for (int p = 0; p < 4; p++)
        #pragma unroll
        for (int c = 0; c < 8; c++) acc[p][c] = 0.f;
    float kfa = 0.f, kfb = 0.f;

    const int2* __restrict__ E = g_edge;
    int k = s;
    int2 e0, e1;
    if (k + 1 < e) { e0 = E[k]; e1 = E[k + 1]; }
    while (k + 1 < e) {
        // prefetch next pair (array padded by 8; garbage never dereferenced)
        int2 f0 = E[k + 2], f1 = E[k + 3];
        EdgeData d0 = ld_edge(Min, e0.x, l);
        EdgeData d1 = ld_edge(Min, e1.x, l);
        acc_edge(acc, kfa, kfb, d0, __int_as_float(e0.y));
        acc_edge(acc, kfa, kfb, d1, __int_as_float(e1.y));
        k += 2;
        e0 = f0; e1 = f1;
    }
    if (k < e) {
        int2 p = E[k];
        EdgeData d = ld_edge(Min, p.x, l);
        acc_edge(acc, kfa, kfb, d, __int_as_float(p.y));
    }

    // stores: skipped on last hop (Mout never read again)
    if (write_m) {
        __half* row = Mout + (size_t)n * MROW;
        float4* Qp = (float4*)row + l;
        #pragma unroll
        for (int p = 0; p < 4; p++) {
            float4 o;
            __half2* oh = reinterpret_cast<__half2*>(&o);
            oh[0] = __floats2half2_rn(acc[p][0], acc[p][1]);
            oh[1] = __floats2half2_rn(acc[p][2], acc[p][3]);
            oh[2] = __floats2half2_rn(acc[p][4], acc[p][5]);
            oh[3] = __floats2half2_rn(acc[p][6], acc[p][7]);
            Qp[p * 32] = o;
        }
        ((__half2*)(row + 1024))[l] = __floats2half2_rn(kfa, kfb);
    }

    // ---- epilogue: H = Q·M, C = Q·Kf, hidden += gamma/C * H -----------------
    // lane l holds Kf channels (2l, 2l+1) in (kfa, kfb); Q loaded to match.
    float2 q2 = *(const float2*)(g_Q + n * HC + 2 * l);
    float qa = q2.x, qb = q2.y;

    // C per head: head hd owns lanes hd*8..hd*8+7
    float t0 = qa * kfa + qb * kfb;
    #pragma unroll
    for (int mask = 1; mask <= 4; mask <<= 1)
        t0 += __shfl_xor_sync(F, t0, mask);
    float cc[4];
    cc[0] = __shfl_sync(F, t0, 0)  + CSTADD;
    cc[1] = __shfl_sync(F, t0, 8)  + CSTADD;
    cc[2] = __shfl_sync(F, t0, 16) + CSTADD;
    cc[3] = __shfl_sync(F, t0, 24) + CSTADD;

    // gamma = hopwise[hop+1] * softmax(headwise[:,hop])
    float h0 = headwise[0 * KHOP + hop];
    float h1 = headwise[1 * KHOP + hop];
    float h2 = headwise[2 * KHOP + hop];
    float h3 = headwise[3 * KHOP + hop];
    float mx = fmaxf(fmaxf(h0, h1), fmaxf(h2, h3));
    float e0s = expf(h0 - mx), e1s = expf(h1 - mx), e2s = expf(h2 - mx), e3s = expf(h3 - mx);
    float denom = e0s + e1s + e2s + e3s;
    float hw = hopwise[hop + 1] / denom;
    float sc[4];
    sc[0] = hw * e0s / cc[0];
    sc[1] = hw * e1s / cc[1];
    sc[2] = hw * e2s / cc[2];
    sc[3] = hw * e3s / cc[3];

    // H: lane holds M rows i=l>>1 (acc[hd][0..7] = 8 cols at j-block l&1).
    // Q[hd][i_] lives at lane hd*8 + (i_>>1), component i_&1.
    int i_ = l >> 1;
    int srcl_off = i_ >> 1;
    int comp = i_ & 1;
    #pragma unroll
    for (int hd = 0; hd < 4; hd++) {
        int srcl = hd * 8 + srcl_off;
        float sa = __shfl_sync(F, qa, srcl);
        float sb = __shfl_sync(F, qb, srcl);
        float qi = comp ? sb : sa;
        float p0 = qi * acc[hd][0], p1 = qi * acc[hd][1];
        float p2 = qi * acc[hd][2], p3 = qi * acc[hd][3];
        float p4 = qi * acc[hd][4], p5 = qi * acc[hd][5];
        float p6 = qi * acc[hd][6], p7 = qi * acc[hd][7];
        #pragma unroll
        for (int mask = 2; mask <= 16; mask <<= 1) {
            p0 += __shfl_xor_sync(F, p0, mask);
            p1 += __shfl_xor_sync(F, p1, mask);
            p2 += __shfl_xor_sync(F, p2, mask);
            p3 += __shfl_xor_sync(F, p3, mask);
            p4 += __shfl_xor_sync(F, p4, mask);
            p5 += __shfl_xor_sync(F, p5, mask);
            p6 += __shfl_xor_sync(F, p6, mask);
            p7 += __shfl_xor_sync(F, p7, mask);
        }
        if (l < 2) {
            float g = sc[hd];
            float* d = &hsm[w][hd * 16 + l * 8];
            d[0] = p0 * g; d[1] = p1 * g; d[2] = p2 * g; d[3] = p3 * g;
            d[4] = p4 * g; d[5] = p5 * g; d[6] = p6 * g; d[7] = p7 * g;
        }
    }
    __syncwarp();
    if (l < 16) {
        float4* hp = (float4*)(g_hid + n * HC) + l;
        float4 add = *((float4*)hsm[w] + l);
        float4 hv = *hp;
        hv.x += add.x; hv.y += add.y; hv.z += add.z; hv.w += add.w;
        *hp = hv;
    }
}

// ---------------- 8. output projection hidden[N,64] @ Wo[64,16] + bo ----------
__global__ void k_wo(const float* __restrict__ Wo, const float* __restrict__ bo,
                     float* __restrict__ out_hidden, int write_out) {
    int idx = blockIdx.x * blockDim.x + threadIdx.x;
    if (idx >= NN * 16) return;
    int n = idx >> 4, cc = idx & 15;
    float acc = bo[cc];
    #pragma unroll 8
    for (int k = 0; k < HC; k++) acc += g_hid[n * HC + k] * Wo[k * 16 + cc];
    g_hid16[idx] = acc;
    if (write_out) out_hidden[idx] = acc;
}

// ---------------- 9. edge regression head (packed f32x2 FMA) ----------------
__global__ __launch_bounds__(256) void k_edge(
    const int* __restrict__ fei,
    const float* __restrict__ Wf1, const float* __restrict__ bf1,
    const float* __restrict__ Wf2, const float* __restrict__ bf2,
    float* __restrict__ out)
{
    __shared__ float w1[32 * 16];
    __shared__ float b1[16];
    __shared__ float w2[16];
    int t = threadIdx.x;
    for (int i = t; i < 512; i += 256) w1[i] = Wf1[i];
    if (t < 16) { b1[t] = bf1[t]; w2[t] = Wf2[t]; }
    __syncthreads();

    int e = blockIdx.x * blockDim.x + t;
    if (e >= FEE) return;
    int srow = fei[e];
    int drow = fei[FEE + e];

    float he[32];
    {
        const float4* hp = (const float4*)(g_hid16 + srow * 16);
        float4 v;
        v = hp[0]; he[0] = v.x; he[1] = v.y; he[2] = v.z; he[3] = v.w;
        v = hp[1]; he[4] = v.x; he[5] = v.y; he[6] = v.z; he[7] = v.w;
        v = hp[2]; he[8] = v.x; he[9] = v.y; he[10] = v.z; he[11] = v.w;
        v = hp[3]; he[12] = v.x; he[13] = v.y; he[14] = v.z; he[15] = v.w;
        const float4* hq = (const float4*)(g_hid16 + drow * 16);
        v = hq[0]; he[16] = v.x; he[17] = v.y; he[18] = v.z; he[19] = v.w;
        v = hq[1]; he[20] = v.x; he[21] = v.y; he[22] = v.z; he[23] = v.w;
        v = hq[2]; he[24] = v.x; he[25] = v.y; he[26] = v.z; he[27] = v.w;
        v = hq[3]; he[28] = v.x; he[29] = v.y; he[30] = v.z; he[31] = v.w;
    }

    // 16 accumulators as 8 packed f32x2
    unsigned long long acc8[8];
    {
        const unsigned long long* bu = (const unsigned long long*)b1;
        #pragma unroll
        for (int j = 0; j < 8; j++) acc8[j] = bu[j];
    }
    #pragma unroll
    for (int k = 0; k < 32; k++) {
        float hv = he[k];
        unsigned long long hv2;
        asm("mov.b64 %0, {%1, %1};" : "=l"(hv2) : "f"(hv));
        const ulonglong2* wr = (const ulonglong2*)(w1 + k * 16);
        #pragma unroll
        for (int j = 0; j < 4; j++) {
            ulonglong2 wp = wr[j];
            asm("fma.rn.f32x2 %0, %1, %2, %0;" : "+l"(acc8[2 * j])     : "l"(hv2), "l"(wp.x));
            asm("fma.rn.f32x2 %0, %1, %2, %0;" : "+l"(acc8[2 * j + 1]) : "l"(hv2), "l"(wp.y));
        }
    }
    float outv = bf2[0];
    #pragma unroll
    for (int j = 0; j < 8; j++) {
        float lo, hi;
        asm("mov.b64 {%0, %1}, %2;" : "=f"(lo), "=f"(hi) : "l"(acc8[j]));
        outv += silu(lo) * w2[2 * j] + silu(hi) * w2[2 * j + 1];
    }
    out[e] = outv;
}

// ---------------- launch ----------------
extern "C" void kernel_launch(void* const* d_in, const int* in_sizes, int n_in,
                              void* d_out, int out_size) {
    const float* x   = (const float*)d_in[0];
    const int* ei    = (const int*)d_in[1];
    const int* fei   = (const int*)d_in[2];
    const int* ts    = (const int*)d_in[3];
    const float* Wi  = (const float*)d_in[4];
    const float* bi  = (const float*)d_in[5];
    const float* Wt1 = (const float*)d_in[6];
    const float* bt1 = (const float*)d_in[7];
    const float* Wt2 = (const float*)d_in[8];
    const float* bt2 = (const float*)d_in[9];
    const float* WQ  = (const float*)d_in[10];
    const float* bQ  = (const float*)d_in[11];
    const float* WK  = (const float*)d_in[12];
    const float* bK  = (const float*)d_in[13];
    const float* WV  = (const float*)d_in[14];
    const float* bV  = (const float*)d_in[15];
    const float* Wo  = (const float*)d_in[16];
    const float* bo  = (const float*)d_in[17];
    const float* hopwise  = (const float*)d_in[18];
    const float* headwise = (const float*)d_in[19];
    const float* Wf1 = (const float*)d_in[20];
    const float* bf1 = (const float*)d_in[21];
    const float* Wf2 = (const float*)d_in[22];
    const float* bf2 = (const float*)d_in[23];
    float* out = (float*)d_out;

    static __half* pM0 = nullptr;
    static __half* pM1;
    static int* pCnt;
    if (!pM0) {
        cudaGetSymbolAddress((void**)&pM0, g_Mh);
        pM1 = pM0 + (size_t)NN * MROW;
        cudaGetSymbolAddress((void**)&pCnt, g_cnt2);
    }

    int write_hidden = (out_size >= FEE + NN * 16) ? 1 : 0;
    float* out_hidden = out + FEE;

    cudaMemsetAsync(pCnt, 0, 2 * NN * sizeof(int));

    k_deg<<<(EE + 255) / 256, 256>>>(ei);
    k_scan_temb<<<1 + NUMT, 1024>>>(Wt1, bt1, Wt2, bt2);
    k_csr<<<(EE + 255) / 256, 256>>>(ei);
    k_feat<<<NN / 32, 256>>>(x, ts, Wi, bi, WQ, bQ, WK, bK, WV, bV, hopwise);

    // hops with ping-pong buffers; last hop skips M/Kf stores
    k_hop<<<NN / 8, 256>>>(pM0, pM1, hopwise, headwise, 0, 1);
    k_hop<<<NN / 8, 256>>>(pM1, pM0, hopwise, headwise, 1, 1);
    k_hop<<<NN / 8, 256>>>(pM0, pM1, hopwise, headwise, 2, 0);

    k_wo<<<(NN * 16 + 255) / 256, 256>>>(Wo, bo, out_hidden, write_hidden);
    k_edge<<<(FEE + 255) / 256, 256>>>(fei, Wf1, bf1, Wf2, bf2, out);
}